// round 16
// baseline (speedup 1.0000x reference)
#include <cuda_runtime.h>
#include <cuda_bf16.h>
#include <math.h>
#include <stdint.h>

// Problem constants
#define BB 2
#define SS 2048
#define DD 1024
#define HH 16
#define HD 64
#define D3 (3 * DD)
#define MM (BB * SS)   // 4096

// ---------------------------------------------------------------------------
// Global scratch (no allocation allowed)
// ---------------------------------------------------------------------------
__device__ float g_qkv[MM * D3];                 // fp32; Q/K interleaved+rtf, V rtf
__device__ __nv_bfloat16 g_xhi[MM * DD],  g_xlo[MM * DD];    // x hi/lo, pair-ilv
__device__ __nv_bfloat16 g_arhi[MM * DD], g_arlo[MM * DD];   // attn out hi/lo
__device__ __nv_bfloat16 g_wqthi[D3 * DD], g_wqtlo[D3 * DD]; // Wqkv^T [N][K]
__device__ __nv_bfloat16 g_wothi[DD * DD], g_wotlo[DD * DD]; // Wout^T [N][K]

// ---------------------------------------------------------------------------
// Helpers
// ---------------------------------------------------------------------------
__device__ __forceinline__ float rtf(float x) {       // fp32 -> tf32 RN
    return __int_as_float(__float_as_int(x) + 0x1000);
}
__device__ __forceinline__ unsigned rtu(float x) {
    return (unsigned)(__float_as_int(x) + 0x1000);
}
__device__ __forceinline__ float ex2(float x) {       // MUFU exp2
    float r;
    asm("ex2.approx.f32 %0, %1;" : "=f"(r) : "f"(x));
    return r;
}
__device__ __forceinline__ uint32_t smem_u32(const void* p) {
    uint32_t a;
    asm("{ .reg .u64 t; cvta.to.shared.u64 t, %1; cvt.u32.u64 %0, t; }"
        : "=r"(a) : "l"(p));
    return a;
}
// Split v0,v1 into packed bf16 hi and lo words (lo = bf16(v - bf16(v))).
__device__ __forceinline__ void bsplit2(float v0, float v1,
                                        unsigned& h, unsigned& l) {
    unsigned short h0 = __bfloat16_as_ushort(__float2bfloat16(v0));
    float r0 = v0 - __bfloat162float(__ushort_as_bfloat16(h0));
    unsigned short l0 = __bfloat16_as_ushort(__float2bfloat16(r0));
    unsigned short h1 = __bfloat16_as_ushort(__float2bfloat16(v1));
    float r1 = v1 - __bfloat162float(__ushort_as_bfloat16(h1));
    unsigned short l1 = __bfloat16_as_ushort(__float2bfloat16(r1));
    h = (unsigned)h0 | ((unsigned)h1 << 16);
    l = (unsigned)l0 | ((unsigned)l1 << 16);
}
#define CP_ASYNC16(dst, src)                                                  \
    asm volatile("cp.async.cg.shared.global [%0], [%1], 16;"                  \
                 :: "r"(dst), "l"(src) : "memory")
#define CP_COMMIT() asm volatile("cp.async.commit_group;" ::: "memory")
#define CP_WAIT1()  asm volatile("cp.async.wait_group 1;" ::: "memory")

#define MMA_TF32(d, a, b)                                                     \
    asm volatile(                                                             \
        "mma.sync.aligned.m16n8k8.row.col.f32.tf32.tf32.f32 "                 \
        "{%0,%1,%2,%3}, {%4,%5,%6,%7}, {%8,%9}, {%0,%1,%2,%3};"               \
        : "+f"((d)[0]), "+f"((d)[1]), "+f"((d)[2]), "+f"((d)[3])              \
        : "r"((a)[0]), "r"((a)[1]), "r"((a)[2]), "r"((a)[3]),                 \
          "r"((b)[0]), "r"((b)[1]))

#define MMA_BF16(d, a, b)                                                     \
    asm volatile(                                                             \
        "mma.sync.aligned.m16n8k16.row.col.f32.bf16.bf16.f32 "                \
        "{%0,%1,%2,%3}, {%4,%5,%6,%7}, {%8,%9}, {%0,%1,%2,%3};"               \
        : "+f"((d)[0]), "+f"((d)[1]), "+f"((d)[2]), "+f"((d)[3])              \
        : "r"((a)[0]), "r"((a)[1]), "r"((a)[2]), "r"((a)[3]),                 \
          "r"((b)[0]), "r"((b)[1]))

// ---------------------------------------------------------------------------
// Preprocess: split fp32 -> bf16 hi/lo with pair-interleave.
// Pair j (k=2j,2j+1) of each 16-element group goes to slot (j&3)*2 + (j>>2),
// so a thread's LDS.64 at byte 8t yields k-pairs (2t) and (2t+8) = a0/a2.
// ---------------------------------------------------------------------------
__global__ void conv_split(const float4* __restrict__ src,
                           uint4* __restrict__ hi, uint4* __restrict__ lo,
                           int n16)
{
    int i = blockIdx.x * blockDim.x + threadIdx.x;   // one 16-element group
    if (i >= n16) return;
    float v[16];
    #pragma unroll
    for (int q = 0; q < 4; q++) {
        float4 f = src[i * 4 + q];
        v[q * 4 + 0] = f.x; v[q * 4 + 1] = f.y;
        v[q * 4 + 2] = f.z; v[q * 4 + 3] = f.w;
    }
    unsigned hw[8], lw[8];
    #pragma unroll
    for (int j = 0; j < 8; j++) {
        const int pos = (j & 3) * 2 + (j >> 2);
        bsplit2(v[2 * j], v[2 * j + 1], hw[pos], lw[pos]);
    }
    hi[i * 2]     = make_uint4(hw[0], hw[1], hw[2], hw[3]);
    hi[i * 2 + 1] = make_uint4(hw[4], hw[5], hw[6], hw[7]);
    lo[i * 2]     = make_uint4(lw[0], lw[1], lw[2], lw[3]);
    lo[i * 2 + 1] = make_uint4(lw[4], lw[5], lw[6], lw[7]);
}

// W [K][N] fp32 -> Wt [N][K] bf16 hi/lo, pair-interleaved
__global__ void wtrans_split(const float* __restrict__ W,
                             unsigned* __restrict__ Thi,
                             unsigned* __restrict__ Tlo, int K, int N)
{
    __shared__ float tile[32][33];
    const int k0 = blockIdx.y * 32, n0 = blockIdx.x * 32;
    const int tx = threadIdx.x, ty = threadIdx.y;   // 32 x 8
    #pragma unroll
    for (int i = 0; i < 32; i += 8)
        tile[ty + i][tx] = W[(size_t)(k0 + ty + i) * N + n0 + tx];
    __syncthreads();
    #pragma unroll
    for (int jj = 0; jj < 2; jj++) {
        const int j  = ty + jj * 8;                 // pair index in 32-k tile
        const int jg = j & 7;
        const int pos = (j >> 3) * 16 + ((jg & 3) * 2 + (jg >> 2)) * 2;
        unsigned h, l;
        bsplit2(tile[2 * j][tx], tile[2 * j + 1][tx], h, l);
        const size_t o = ((size_t)(n0 + tx) * K + k0 + pos) >> 1;
        Thi[o] = h;
        Tlo[o] = l;
    }
}

// ---------------------------------------------------------------------------
// BF16x3 GEMM: C[M,N] = A[M,K] @ Bt[N,K]^T + bias, fp32 accumulate.
// D = Ahi*Bhi + Ahi*Blo + Alo*Bhi  (error ~2^-15 rel, better than tf32).
// Block 128x128x32, 8 warps (2m x 4n), warp tile 64x32, 2-stage cp.async,
// 96 KB smem -> 2 CTAs/SM. 96 MMA issues/chunk vs tf32's 128 (-25%).
// RSB=96: 16B-aligned rows for cp.async (72 faulted: odd rows 8-mod-16)
// AND conflict-free uint2 fragment loads (banks (24g+2t)%32 distinct/phase).
// mode: 0 = plain fp32 out. 1 = qkv: rtf; k-interleave cols < 2048 (Q/K).
// ---------------------------------------------------------------------------
#define TG_BM 128
#define TG_BN 128
#define TG_BK 32                 // bf16 elements per chunk
#define RSB   96                 // bytes per smem row (64 data + 32 pad)
#define MAT_B (128 * RSB)        // 12288 bytes per matrix tile
#define STG_B (4 * MAT_B)        // 49152 per stage (Ahi,Alo,Bhi,Blo)
#define TG_SMEM (2 * STG_B)      // 98304 bytes

__device__ __forceinline__ void g_stage(uint32_t base,
                                        const __nv_bfloat16* __restrict__ Ahi,
                                        const __nv_bfloat16* __restrict__ Alo,
                                        const __nv_bfloat16* __restrict__ Bhi,
                                        const __nv_bfloat16* __restrict__ Blo,
                                        int bm0, int bn0, int kc, int K, int tid)
{
    #pragma unroll
    for (int it = 0; it < 2; it++) {
        const int u = tid + it * 256;       // 512 chunks per matrix
        const int row = u >> 2, seg = u & 3;
        const uint32_t dst = base + row * RSB + seg * 16;
        const size_t ga = (size_t)(bm0 + row) * K + kc + seg * 8;
        const size_t gb = (size_t)(bn0 + row) * K + kc + seg * 8;
        CP_ASYNC16(dst,             Ahi + ga);
        CP_ASYNC16(dst + MAT_B,     Alo + ga);
        CP_ASYNC16(dst + 2 * MAT_B, Bhi + gb);
        CP_ASYNC16(dst + 3 * MAT_B, Blo + gb);
    }
    CP_COMMIT();
}

__global__ void __launch_bounds__(256, 2)
tgemm_bf16(const __nv_bfloat16* __restrict__ Ahi,
           const __nv_bfloat16* __restrict__ Alo,
           const __nv_bfloat16* __restrict__ Bhi,
           const __nv_bfloat16* __restrict__ Blo,
           const float* __restrict__ bias, float* __restrict__ C,
           int N, int K, int mode)
{
    extern __shared__ char smc[];
    const uint32_t smb = smem_u32(smc);

    const int tid  = threadIdx.x;
    const int lane = tid & 31, wid = tid >> 5;
    const int g = lane >> 2, t = lane & 3;
    const int wm = wid & 1, wn = wid >> 1;          // 2 m-warps x 4 n-warps
    const int bm0 = blockIdx.y * TG_BM, bn0 = blockIdx.x * TG_BN;

    float c[4][4][4];
    #pragma unroll
    for (int mt = 0; mt < 4; mt++)
        #pragma unroll
        for (int nt = 0; nt < 4; nt++)
            #pragma unroll
            for (int r = 0; r < 4; r++) c[mt][nt][r] = 0.f;

    const int NC = K / TG_BK;    // 32
    g_stage(smb,         Ahi, Alo, Bhi, Blo, bm0, bn0, 0,     K, tid);
    g_stage(smb + STG_B, Ahi, Alo, Bhi, Blo, bm0, bn0, TG_BK, K, tid);

    for (int cix = 0; cix < NC; cix++) {
        CP_WAIT1();
        __syncthreads();            // all threads' copies for chunk cix visible

        const char* stg = smc + (cix & 1) * STG_B;
        #pragma unroll
        for (int ks = 0; ks < 2; ks++) {
            const int kb = ks * 32 + t * 8;   // byte offset within row
            unsigned ahi[4][4], bhi[4][2];
            #pragma unroll
            for (int mt = 0; mt < 4; mt++) {
                const int ro = (wm * 64 + mt * 16 + g) * RSB + kb;
                uint2 v0 = *(const uint2*)(stg + ro);
                uint2 v1 = *(const uint2*)(stg + ro + 8 * RSB);
                ahi[mt][0] = v0.x; ahi[mt][1] = v1.x;
                ahi[mt][2] = v0.y; ahi[mt][3] = v1.y;
            }
            #pragma unroll
            for (int nt = 0; nt < 4; nt++) {
                const int co = (wn * 32 + nt * 8 + g) * RSB + kb;
                uint2 v = *(const uint2*)(stg + 2 * MAT_B + co);
                bhi[nt][0] = v.x; bhi[nt][1] = v.y;
            }
            #pragma unroll
            for (int mt = 0; mt < 4; mt++)
                #pragma unroll
                for (int nt = 0; nt < 4; nt++)
                    MMA_BF16(c[mt][nt], ahi[mt], bhi[nt]);

            unsigned blo[4][2];
            #pragma unroll
            for (int nt = 0; nt < 4; nt++) {
                const int co = (wn * 32 + nt * 8 + g) * RSB + kb;
                uint2 v = *(const uint2*)(stg + 3 * MAT_B + co);
                blo[nt][0] = v.x; blo[nt][1] = v.y;
            }
            #pragma unroll
            for (int mt = 0; mt < 4; mt++)
                #pragma unroll
                for (int nt = 0; nt < 4; nt++)
                    MMA_BF16(c[mt][nt], ahi[mt], blo[nt]);

            unsigned alo[4][4];
            #pragma unroll
            for (int mt = 0; mt < 4; mt++) {
                const int ro = (wm * 64 + mt * 16 + g) * RSB + kb;
                uint2 v0 = *(const uint2*)(stg + MAT_B + ro);
                uint2 v1 = *(const uint2*)(stg + MAT_B + ro + 8 * RSB);
                alo[mt][0] = v0.x; alo[mt][1] = v1.x;
                alo[mt][2] = v0.y; alo[mt][3] = v1.y;
            }
            #pragma unroll
            for (int mt = 0; mt < 4; mt++)
                #pragma unroll
                for (int nt = 0; nt < 4; nt++)
                    MMA_BF16(c[mt][nt], alo[mt], bhi[nt]);
        }
        __syncthreads();            // WAR: buffer about to be restaged
        if (cix + 2 < NC)
            g_stage(smb + (cix & 1) * STG_B, Ahi, Alo, Bhi, Blo,
                    bm0, bn0, (cix + 2) * TG_BK, K, tid);
        else
            CP_COMMIT();            // keep wait-group accounting uniform
    }

    // epilogue (same accumulator layout as tf32 m16n8k8)
    const bool ilv = (mode == 1) && (bn0 < 2048);
    const int p0 = 2 * (2 * t & 3) + (t >> 1);
    const int p1 = 2 * ((2 * t + 1) & 3) + (t >> 1);
    #pragma unroll
    for (int mt = 0; mt < 4; mt++) {
        const int row = bm0 + wm * 64 + mt * 16 + g;
        #pragma unroll
        for (int nt = 0; nt < 4; nt++) {
            const int col = bn0 + wn * 32 + nt * 8 + 2 * t;
            float2 bv = *(const float2*)(bias + col);
            float v00 = c[mt][nt][0] + bv.x, v01 = c[mt][nt][1] + bv.y;
            float v10 = c[mt][nt][2] + bv.x, v11 = c[mt][nt][3] + bv.y;
            if (mode == 1) {
                v00 = rtf(v00); v01 = rtf(v01); v10 = rtf(v10); v11 = rtf(v11);
            }
            float* r0p = C + (size_t)row * N;
            float* r1p = C + (size_t)(row + 8) * N;
            if (ilv) {
                const int gb = bn0 + wn * 32 + nt * 8;
                r0p[gb + p0] = v00; r0p[gb + p1] = v01;
                r1p[gb + p0] = v10; r1p[gb + p1] = v11;
            } else {
                *(float2*)(r0p + col) = make_float2(v00, v01);
                *(float2*)(r1p + col) = make_float2(v10, v11);
            }
        }
    }
}

// ---------------------------------------------------------------------------
// TF32 flash attention (round-13 structure): 4 warps/CTA, 32 q-rows/warp,
// q-tile 128, 2 CTAs/SM for cross-CTA phase overlap. Epilogue writes
// bf16 hi/lo pair-interleaved directly into GEMM2's A operand.
// grid (S/128, B*H), 128 threads.
// ---------------------------------------------------------------------------
#define KVSTR 72
#define PSTR  72
#define KV_FLT (64 * KVSTR)                      // 4608 floats per tile
#define AT_SMEM ((4 * KV_FLT + 4 * 32 * PSTR) * 4)   // 110592 B
#define QSCALE 0.18033688f                       // (1/sqrt(64)) * log2(e)

__device__ __forceinline__ void a_stage(uint32_t kb, uint32_t vb,
                                        const float* __restrict__ base,
                                        int kt, int h, int tid)
{
    const float* kg = base + DD + h * HD;
    const float* vg = base + 2 * DD + h * HD;
    #pragma unroll
    for (int it = 0; it < 8; it++) {
        const int u = tid + it * 128;
        const int row = u >> 4, cseg = u & 15;
        CP_ASYNC16(kb + row * 288 + cseg * 16,
                   kg + (size_t)(kt + row) * D3 + cseg * 4);
    }
    #pragma unroll
    for (int it = 0; it < 8; it++) {
        const int u = tid + it * 128;
        const int row = u >> 4, cseg = u & 15;
        CP_ASYNC16(vb + row * 288 + cseg * 16,
                   vg + (size_t)(kt + row) * D3 + cseg * 4);
    }
    CP_COMMIT();
}

__global__ void __launch_bounds__(128, 2)
attn_tc_kernel(const float* __restrict__ qkv,
               __nv_bfloat16* __restrict__ outHi,
               __nv_bfloat16* __restrict__ outLo)
{
    extern __shared__ float sm[];
    const uint32_t smb = smem_u32(sm);
    float* Ksb[2] = { sm,          sm + 2 * KV_FLT };
    float* Vsb[2] = { sm + KV_FLT, sm + 3 * KV_FLT };
    const uint32_t kaddr[2] = { smb, smb + 2 * KV_FLT * 4 };
    const uint32_t vaddr[2] = { smb + KV_FLT * 4, smb + 3 * KV_FLT * 4 };

    const int tid  = threadIdx.x;
    const int lane = tid & 31, wid = tid >> 5;       // wid 0..3
    const int g = lane >> 2, t = lane & 3;
    const int bh = blockIdx.y, b = bh >> 4, h = bh & 15;
    const int q0 = blockIdx.x * 128;
    const int rb = wid * 32;

    float* Pw = sm + 4 * KV_FLT + wid * 32 * PSTR;

    const float* base = qkv + (size_t)b * SS * D3;

    a_stage(kaddr[0], vaddr[0], base, 0, h, tid);

    // Q fragments (gmem tf32-rounded + interleaved: pos 2t,2t+1 = logical t,t+4)
    unsigned qa[2][8][4];
    {
        const float* qp = base + (size_t)q0 * D3 + h * HD;
        #pragma unroll
        for (int u = 0; u < 2; u++) {
            const int r0 = rb + u * 16 + g;
            #pragma unroll
            for (int kc = 0; kc < 8; kc++) {
                float2 v0 = *(const float2*)(qp + (size_t)r0 * D3 + kc * 8 + 2 * t);
                float2 v1 = *(const float2*)(qp + (size_t)(r0 + 8) * D3 + kc * 8 + 2 * t);
                qa[u][kc][0] = rtu(v0.x * QSCALE); qa[u][kc][2] = rtu(v0.y * QSCALE);
                qa[u][kc][1] = rtu(v1.x * QSCALE); qa[u][kc][3] = rtu(v1.y * QSCALE);
            }
        }
    }

    float o[2][8][4];
    #pragma unroll
    for (int u = 0; u < 2; u++)
        #pragma unroll
        for (int nt = 0; nt < 8; nt++)
            #pragma unroll
            for (int r = 0; r < 4; r++) o[u][nt][r] = 0.f;
    float m[2][2] = { { -1e30f, -1e30f }, { -1e30f, -1e30f } };
    float l[2][2] = { { 0.f, 0.f }, { 0.f, 0.f } };

    const int NT = SS / 64;   // 32
    for (int i = 0; i < NT; i++) {
        const int buf = i & 1;
        __syncthreads();                      // WAR: prev consume of buf^1 done
        if (i + 1 < NT)
            a_stage(kaddr[buf ^ 1], vaddr[buf ^ 1], base, (i + 1) * 64, h, tid);
        else
            CP_COMMIT();
        CP_WAIT1();
        __syncthreads();                      // RAW: all copies of buf visible

        const float* Ks = Ksb[buf];
        const float* Vs = Vsb[buf];

        float s[2][8][4];
        #pragma unroll
        for (int u = 0; u < 2; u++)
            #pragma unroll
            for (int nt = 0; nt < 8; nt++)
                #pragma unroll
                for (int r = 0; r < 4; r++) s[u][nt][r] = 0.f;
        #pragma unroll
        for (int kc = 0; kc < 8; kc++) {
            #pragma unroll
            for (int nt = 0; nt < 8; nt++) {
                uint2 kv = *(const uint2*)(Ks + (nt * 8 + g) * KVSTR + kc * 8 + 2 * t);
                unsigned bf[2] = { kv.x, kv.y };
                MMA_TF32(s[0][nt], qa[0][kc], bf);
                MMA_TF32(s[1][nt], qa[1][kc], bf);
            }
        }

        // online softmax per row-group (base-2 domain)
        #pragma unroll
        for (int u = 0; u < 2; u++) {
            float cm0 = s[u][0][0], cm1 = s[u][0][2];
            #pragma unroll
            for (int nt = 0; nt < 8; nt++) {
                cm0 = fmaxf(cm0, fmaxf(s[u][nt][0], s[u][nt][1]));
                cm1 = fmaxf(cm1, fmaxf(s[u][nt][2], s[u][nt][3]));
            }
            cm0 = fmaxf(cm0, __shfl_xor_sync(0xffffffffu, cm0, 1));
            cm0 = fmaxf(cm0, __shfl_xor_sync(0xffffffffu, cm0, 2));
            cm1 = fmaxf(cm1, __shfl_xor_sync(0xffffffffu, cm1, 1));
            cm1 = fmaxf(cm1, __shfl_xor_sync(0xffffffffu, cm1, 2));
            const float mn0 = fmaxf(m[u][0], cm0);
            const float mn1 = fmaxf(m[u][1], cm1);
            const float corr0 = ex2(m[u][0] - mn0);
            const float corr1 = ex2(m[u][1] - mn1);
            m[u][0] = mn0; m[u][1] = mn1;

            float rs0 = 0.f, rs1 = 0.f;
            #pragma unroll
            for (int nt = 0; nt < 8; nt++) {
                float p;
                p = rtf(ex2(s[u][nt][0] - mn0)); s[u][nt][0] = p; rs0 += p;
                p = rtf(ex2(s[u][nt][1] - mn0)); s[u][nt][1] = p; rs0 += p;
                p = rtf(ex2(s[u][nt][2] - mn1)); s[u][nt][2] = p; rs1 += p;
                p = rtf(ex2(s[u][nt][3] - mn1)); s[u][nt][3] = p; rs1 += p;
                o[u][nt][0] *= corr0; o[u][nt][1] *= corr0;
                o[u][nt][2] *= corr1; o[u][nt][3] *= corr1;
            }
            rs0 += __shfl_xor_sync(0xffffffffu, rs0, 1);
            rs0 += __shfl_xor_sync(0xffffffffu, rs0, 2);
            rs1 += __shfl_xor_sync(0xffffffffu, rs1, 1);
            rs1 += __shfl_xor_sync(0xffffffffu, rs1, 2);
            l[u][0] = l[u][0] * corr0 + rs0;
            l[u][1] = l[u][1] * corr1 + rs1;
        }

        // P -> per-warp smem, then PV
        #pragma unroll
        for (int u = 0; u < 2; u++) {
            #pragma unroll
            for (int nt = 0; nt < 8; nt++) {
                *(float2*)(Pw + (u * 16 + g) * PSTR + nt * 8 + 2 * t) =
                    make_float2(s[u][nt][0], s[u][nt][1]);
                *(float2*)(Pw + (u * 16 + g + 8) * PSTR + nt * 8 + 2 * t) =
                    make_float2(s[u][nt][2], s[u][nt][3]);
            }
        }
        __syncwarp();
        #pragma unroll
        for (int kc = 0; kc < 8; kc++) {
            unsigned pa[2][4];
            #pragma unroll
            for (int u = 0; u < 2; u++) {
                pa[u][0] = __float_as_uint(Pw[(u * 16 + g) * PSTR + kc * 8 + t]);
                pa[u][1] = __float_as_uint(Pw[(u * 16 + g + 8) * PSTR + kc * 8 + t]);
                pa[u][2] = __float_as_uint(Pw[(u * 16 + g) * PSTR + kc * 8 + t + 4]);
                pa[u][3] = __float_as_uint(Pw[(u * 16 + g + 8) * PSTR + kc * 8 + t + 4]);
            }
            #pragma unroll
            for (int nt = 0; nt < 8; nt++) {
                unsigned bf[2];
                bf[0] = __float_as_uint(Vs[(kc * 8 + t) * KVSTR + nt * 8 + g]);
                bf[1] = __float_as_uint(Vs[(kc * 8 + t + 4) * KVSTR + nt * 8 + g]);
                MMA_TF32(o[0][nt], pa[0], bf);
                MMA_TF32(o[1][nt], pa[1], bf);
            }
        }
        __syncwarp();
    }

    // epilogue: normalize, split to bf16 hi/lo, pair-interleaved writes.
    // For logical cols c=nt*8+2t, c+1: interleaved positions pos, pos+1 with
    // pos = (nt>>1)*16 + 4t + 2*(nt&1)  (even -> 4B-aligned uint writes).
    #pragma unroll
    for (int u = 0; u < 2; u++) {
        const float inv0 = 1.f / l[u][0];
        const float inv1 = 1.f / l[u][1];
        const size_t be = (size_t)b * SS * DD
                        + (size_t)(q0 + rb + u * 16 + g) * DD + h * HD;
        #pragma unroll
        for (int nt = 0; nt < 8; nt++) {
            const int pos = (nt >> 1) * 16 + 4 * t + 2 * (nt & 1);
            unsigned h0, l0, h1, l1;
            bsplit2(o[u][nt][0] * inv0, o[u][nt][1] * inv0, h0, l0);
            bsplit2(o[u][nt][2] * inv1, o[u][nt][3] * inv1, h1, l1);
            ((unsigned*)outHi)[(be + pos) >> 1] = h0;
            ((unsigned*)outLo)[(be + pos) >> 1] = l0;
            ((unsigned*)outHi)[(be + (size_t)8 * DD + pos) >> 1] = h1;
            ((unsigned*)outLo)[(be + (size_t)8 * DD + pos) >> 1] = l1;
        }
    }
}

// ---------------------------------------------------------------------------
// Launch
// ---------------------------------------------------------------------------
extern "C" void kernel_launch(void* const* d_in, const int* in_sizes, int n_in,
                              void* d_out, int out_size)
{
    const float* x     = (const float*)d_in[0];
    const float* W_qkv = (const float*)d_in[1];
    const float* b_qkv = (const float*)d_in[2];
    const float* W_out = (const float*)d_in[3];
    const float* b_out = (const float*)d_in[4];
    float* out = (float*)d_out;

    float* qkv;
    __nv_bfloat16 *xhi, *xlo, *arhi, *arlo, *wqh, *wql, *woh, *wol;
    cudaGetSymbolAddress((void**)&qkv,  g_qkv);
    cudaGetSymbolAddress((void**)&xhi,  g_xhi);
    cudaGetSymbolAddress((void**)&xlo,  g_xlo);
    cudaGetSymbolAddress((void**)&arhi, g_arhi);
    cudaGetSymbolAddress((void**)&arlo, g_arlo);
    cudaGetSymbolAddress((void**)&wqh,  g_wqthi);
    cudaGetSymbolAddress((void**)&wql,  g_wqtlo);
    cudaGetSymbolAddress((void**)&woh,  g_wothi);
    cudaGetSymbolAddress((void**)&wol,  g_wotlo);

    cudaFuncSetAttribute(tgemm_bf16,
                         cudaFuncAttributeMaxDynamicSharedMemorySize, TG_SMEM);
    cudaFuncSetAttribute(attn_tc_kernel,
                         cudaFuncAttributeMaxDynamicSharedMemorySize, AT_SMEM);

    // 0) preprocess: split x and weights into bf16 hi/lo (pair-interleaved)
    {
        int n16 = MM * DD / 16;   // 262144
        conv_split<<<n16 / 256, 256>>>((const float4*)x, (uint4*)xhi, (uint4*)xlo, n16);
        dim3 tb(32, 8);
        wtrans_split<<<dim3(D3 / 32, DD / 32), tb>>>(W_qkv, (unsigned*)wqh,
                                                     (unsigned*)wql, DD, D3);
        wtrans_split<<<dim3(DD / 32, DD / 32), tb>>>(W_out, (unsigned*)woh,
                                                     (unsigned*)wol, DD, DD);
    }
    // 1) QKV projection (bf16x3; mode 1: rtf + Q/K interleave for attention)
    tgemm_bf16<<<dim3(D3 / TG_BN, MM / TG_BM), 256, TG_SMEM>>>(
        xhi, xlo, wqh, wql, b_qkv, qkv, D3, DD, 1);
    // 2) flash attention -> bf16 hi/lo (GEMM2's A operand)
    attn_tc_kernel<<<dim3(SS / 128, BB * HH), 128, AT_SMEM>>>(qkv, arhi, arlo);
    // 3) output projection (bf16x3; mode 0: plain fp32 output)
    tgemm_bf16<<<dim3(DD / TG_BN, MM / TG_BM), 256, TG_SMEM>>>(
        arhi, arlo, woh, wol, b_out, out, DD, DD, 0);
}